// round 8
// baseline (speedup 1.0000x reference)
#include <cuda_runtime.h>
#include <cuda_fp16.h>
#include <cstdint>

// ============================================================================
// y[t, :] = weight[x[t], :] + A[x[t], :] @ B
//   tokens M = 16384, DIM N = 1024, RANK K = 256
// Persistent-CTA version: 296 CTAs (2/SM), each loops over ~3.5 tiles with the
// proven 3-stage cp.async pipeline; next tile's first chunk is prefetched
// during the current tile's epilogue. Weight rows staged into dead buffers.
// ============================================================================
static constexpr int M_TOTAL = 16384;
static constexpr int DIM     = 1024;
static constexpr int RANK    = 256;

static constexpr int TILE_M  = 128;
static constexpr int TILE_N  = 128;
static constexpr int KC      = 64;              // K chunk (halves)
static constexpr int STAGES  = 3;
static constexpr int NTILES  = (M_TOTAL / TILE_M) * (DIM / TILE_N);  // 1024
static constexpr int CTAS    = 296;             // 2 per SM x 148 SMs

// Smem: pitch 72 halves (144 B) -> conflict-free ldmatrix (banks 4i mod 32)
static constexpr int PITCH        = 72;
static constexpr int TILE_HALVES  = 128 * PITCH;            // 9216 halves
static constexpr int TILE_BYTES_S = TILE_HALVES * 2;        // 18432 B
static constexpr int STAGE_BYTES  = 2 * TILE_BYTES_S;       // A + B per stage
static constexpr int SMEM_BYTES   = STAGES * STAGE_BYTES + 512;  // 111104 B

// Weight staging: 64 rows x 528 B (132 floats) = 33792 B, fits in one stage buf
static constexpr int W_PITCH_F = 132;
static constexpr int W_PITCH_B = 528;

// Scratch: half B^T [DIM][RANK] (0.5 MB), gathered half A [M][RANK] (8 MB)
__device__ __half g_Bt[DIM * RANK];
__device__ __half g_Ah[M_TOTAL * RANK];

// ---------------------------------------------------------------------------
__device__ __forceinline__ uint32_t smem_to_u32(const void* p) {
    uint32_t a;
    asm("{ .reg .u64 t; cvta.to.shared.u64 t, %1; cvt.u32.u64 %0, t; }" : "=r"(a) : "l"(p));
    return a;
}
__device__ __forceinline__ void cp_async16(uint32_t dst, const void* src) {
    asm volatile("cp.async.cg.shared.global [%0], [%1], 16;" :: "r"(dst), "l"(src));
}
__device__ __forceinline__ void cp_commit() {
    asm volatile("cp.async.commit_group;" ::: "memory");
}
template <int N>
__device__ __forceinline__ void cp_wait() {
    asm volatile("cp.async.wait_group %0;" :: "n"(N) : "memory");
}
__device__ __forceinline__ void ldmatrix_x4(uint32_t& r0, uint32_t& r1,
                                            uint32_t& r2, uint32_t& r3, uint32_t addr) {
    asm volatile("ldmatrix.sync.aligned.m8n8.x4.shared.b16 {%0,%1,%2,%3}, [%4];"
                 : "=r"(r0), "=r"(r1), "=r"(r2), "=r"(r3) : "r"(addr));
}
__device__ __forceinline__ void mma_f16(float* c, const uint32_t* a, const uint32_t* b) {
    asm volatile(
        "mma.sync.aligned.m16n8k16.row.col.f32.f16.f16.f32 "
        "{%0,%1,%2,%3}, {%4,%5,%6,%7}, {%8,%9}, {%0,%1,%2,%3};\n"
        : "+f"(c[0]), "+f"(c[1]), "+f"(c[2]), "+f"(c[3])
        : "r"(a[0]), "r"(a[1]), "r"(a[2]), "r"(a[3]), "r"(b[0]), "r"(b[1]));
}

// ============================================================================
// Kernel 1 (fused prep):
//   blocks [0,256):     transpose+convert B -> g_Bt [DIM][RANK] half
//   blocks [256,2304):  gather+convert A rows: g_Ah[t] = half(A[x[t]]), 8 rows/blk
// ============================================================================
__global__ __launch_bounds__(256)
void prep_kernel(const int* __restrict__ x, const float* __restrict__ A,
                 const float* __restrict__ B) {
    if (blockIdx.x < 256) {
        __shared__ float t[32][33];
        const int n0 = (blockIdx.x & 31) * 32;
        const int k0 = (blockIdx.x >> 5) * 32;
        const int tx = threadIdx.x & 31;
        const int ty = threadIdx.x >> 5;
        #pragma unroll
        for (int j = 0; j < 32; j += 8)
            t[ty + j][tx] = B[(size_t)(k0 + ty + j) * DIM + n0 + tx];
        __syncthreads();
        #pragma unroll
        for (int j = 0; j < 32; j += 8)
            g_Bt[(size_t)(n0 + ty + j) * RANK + k0 + tx] = __float2half_rn(t[tx][ty + j]);
    } else {
        const int row  = (blockIdx.x - 256) * 8 + (threadIdx.x >> 5);
        const int lane = threadIdx.x & 31;
        const int tok  = x[row];
        const float4* src = (const float4*)(A + (size_t)tok * RANK) + lane * 2;
        float4 v0 = src[0], v1 = src[1];
        __half2 h[4];
        h[0] = __floats2half2_rn(v0.x, v0.y);
        h[1] = __floats2half2_rn(v0.z, v0.w);
        h[2] = __floats2half2_rn(v1.x, v1.y);
        h[3] = __floats2half2_rn(v1.z, v1.w);
        *(uint4*)(g_Ah + (size_t)row * RANK + lane * 8) = *(const uint4*)h;
    }
}

// ============================================================================
// Kernel 2: persistent fused GEMM + weight-gather epilogue
//   grid: 296 CTAs; block 256 = 8 warps; warp tile 64x32; 2 CTAs/SM
//   tile id t -> n0 = (t&7)*128 (fastest: concurrent CTAs share A in L2),
//                m0 = (t>>3)*128
// ============================================================================
__global__ __launch_bounds__(256, 2)
void lora_embed_kernel(const int* __restrict__ x,
                       const float* __restrict__ weight,
                       float* __restrict__ out) {
    extern __shared__ __align__(16) char smem[];
    int* s_tok = (int*)(smem + STAGES * STAGE_BYTES);

    const int tid    = threadIdx.x;
    const int wid    = tid >> 5;
    const int lane   = tid & 31;
    const int group  = lane >> 2;   // 0..7
    const int tig    = lane & 3;    // 0..3
    const int warp_m = wid >> 2;    // 0..1
    const int warp_n = wid & 3;     // 0..3

    const uint32_t sb = smem_to_u32(smem);

    // Loader mapping: 2 threads per row, each covers 32 halves (4x16B) / chunk
    const int lrow  = tid >> 1;
    const int lhalf = tid & 1;
    const uint32_t a_dst = sb + (lrow * PITCH + lhalf * 32) * 2;
    const uint32_t b_dst = a_dst + TILE_BYTES_S;

    auto prefetch = [&](const __half* as, const __half* bs, int c) {
        const uint32_t soff = (uint32_t)(c % STAGES) * STAGE_BYTES;
        #pragma unroll
        for (int i = 0; i < 4; i++) {
            cp_async16(a_dst + soff + i * 16, as + c * KC + i * 8);
            cp_async16(b_dst + soff + i * 16, bs + c * KC + i * 8);
        }
        cp_commit();
    };

    // Stage 64 weight rows (half h) into dead stage buffer (1 + h).
    auto stage_weight = [&](int h, int n0) {
        const uint32_t dsm = sb + (uint32_t)(1 + h) * STAGE_BYTES;
        #pragma unroll
        for (int i = 0; i < 8; i++) {
            const int idx = tid + 256 * i;        // 0..2047
            const int row = idx >> 5;             // 0..63
            const int c16 = idx & 31;             // 16B chunk within 512B row
            const int tok = s_tok[h * 64 + row];
            cp_async16(dsm + (uint32_t)(row * W_PITCH_B + c16 * 16),
                       weight + (size_t)tok * DIM + n0 + c16 * 4);
        }
        cp_commit();
    };

    // A ldmatrix lane offset: row = warp_m*64 + (lane&15), koff = (lane>>4)*8
    const uint32_t a_lane_off =
        (uint32_t)(((warp_m * 64 + (lane & 15)) * PITCH + (lane >> 4) * 8) * 2);
    // B ldmatrix lane offset (x4 = mats [nlo klo, nlo khi, nhi klo, nhi khi])
    const uint32_t b_lane_off =
        (uint32_t)(((warp_n * 32 + ((lane >> 4) << 3) + (lane & 7)) * PITCH
                    + ((lane >> 3) & 1) * 8) * 2);

    float acc[4][4][4];

    auto compute = [&](int c) {
        const uint32_t abuf = sb + (uint32_t)(c % STAGES) * STAGE_BYTES;
        const uint32_t bbuf = abuf + (uint32_t)TILE_BYTES_S;
        #pragma unroll
        for (int ks = 0; ks < 4; ks++) {
            const uint32_t k0b = (uint32_t)(ks * 16 * 2);
            uint32_t af[4][4];
            #pragma unroll
            for (int mt = 0; mt < 4; mt++)
                ldmatrix_x4(af[mt][0], af[mt][1], af[mt][2], af[mt][3],
                            abuf + a_lane_off + (uint32_t)(mt * 16 * PITCH * 2) + k0b);
            uint32_t bf[4][2];
            #pragma unroll
            for (int q = 0; q < 2; q++)
                ldmatrix_x4(bf[2 * q][0], bf[2 * q][1], bf[2 * q + 1][0], bf[2 * q + 1][1],
                            bbuf + b_lane_off + (uint32_t)(q * 16 * PITCH * 2) + k0b);
            #pragma unroll
            for (int mt = 0; mt < 4; mt++)
                #pragma unroll
                for (int nt = 0; nt < 4; nt++)
                    mma_f16(acc[mt][nt], af[mt], bf[nt]);
        }
    };

    // ---- persistent tile loop ----
    // First tile's chunk 0 prefetch issued here; every later tile's chunk 0
    // is issued during the previous tile's epilogue (buffer 0 is dead there).
    {
        const int t0 = blockIdx.x;
        const __half* as = g_Ah + (size_t)((t0 >> 3) * TILE_M + lrow) * RANK + lhalf * 32;
        const __half* bs = g_Bt + (size_t)((t0 & 7) * TILE_N + lrow) * RANK + lhalf * 32;
        prefetch(as, bs, 0);
    }

    for (int tile = blockIdx.x; tile < NTILES; tile += CTAS) {
        const int n0 = (tile & 7) * TILE_N;
        const int m0 = (tile >> 3) * TILE_M;
        const __half* a_src = g_Ah + (size_t)(m0 + lrow) * RANK + lhalf * 32;
        const __half* b_src = g_Bt + (size_t)(n0 + lrow) * RANK + lhalf * 32;

        if (tid < 128) s_tok[tid] = x[m0 + tid];
        // Barrier: previous epilogue (reads bufs 1,2 + writes out) must finish
        // before prefetch(1) overwrites buf 1; also orders s_tok for stagers.
        __syncthreads();
        prefetch(a_src, b_src, 1);

        #pragma unroll
        for (int mt = 0; mt < 4; mt++)
            #pragma unroll
            for (int nt = 0; nt < 4; nt++)
                #pragma unroll
                for (int r = 0; r < 4; r++) acc[mt][nt][r] = 0.f;

        // Group stream this tile: [pf0][pf1][pf2][pf3][W0][W1][pfNext0]
        // Every wait<1> leaves exactly one younger group outstanding.
        cp_wait<1>(); __syncthreads(); prefetch(a_src, b_src, 2); compute(0);
        cp_wait<1>(); __syncthreads(); prefetch(a_src, b_src, 3); compute(1);
        cp_wait<1>(); __syncthreads(); stage_weight(0, n0);       compute(2);
        cp_wait<1>(); __syncthreads(); stage_weight(1, n0);       compute(3);
        cp_wait<0>(); __syncthreads();   // weight halves resident in smem

        // Prefetch next tile's chunk 0 into (now dead) buffer 0; it loads
        // while this tile's epilogue runs.
        const int ntile = tile + CTAS;
        if (ntile < NTILES) {
            const __half* na = g_Ah + (size_t)((ntile >> 3) * TILE_M + lrow) * RANK + lhalf * 32;
            const __half* nb = g_Bt + (size_t)((ntile & 7) * TILE_N + lrow) * RANK + lhalf * 32;
            prefetch(na, nb, 0);
        }

        // Epilogue: out = weight_smem + acc. warp_m selects the staged half.
        const float* wsm = (const float*)(smem + (size_t)(1 + warp_m) * STAGE_BYTES);
        #pragma unroll
        for (int mt = 0; mt < 4; mt++) {
            #pragma unroll
            for (int mo = 0; mo < 2; mo++) {
                const int r = mt * 16 + mo * 8 + group;       // 0..63 in half
                const float* wrow = wsm + r * W_PITCH_F;
                float* orow = out + (size_t)(m0 + warp_m * 64 + r) * DIM + n0;
                #pragma unroll
                for (int nt = 0; nt < 4; nt++) {
                    const int col = warp_n * 32 + nt * 8 + tig * 2;
                    float2 w = *(const float2*)(wrow + col);
                    float2 o;
                    o.x = w.x + acc[mt][nt][mo * 2 + 0];
                    o.y = w.y + acc[mt][nt][mo * 2 + 1];
                    *(float2*)(orow + col) = o;
                }
            }
        }
    }
}

// ============================================================================
// Launch
// ============================================================================
extern "C" void kernel_launch(void* const* d_in, const int* in_sizes, int n_in,
                              void* d_out, int out_size) {
    const int*   x      = (const int*)d_in[0];       // [16384] int32
    const float* weight = (const float*)d_in[1];     // [128000, 1024]
    const float* A      = (const float*)d_in[2];     // [128000, 256]
    const float* B      = (const float*)d_in[3];     // [256, 1024]
    float* out          = (float*)d_out;             // [16384, 1024]

    (void)in_sizes; (void)n_in; (void)out_size;

    // Fused prep: 256 transpose blocks + 2048 gather blocks
    prep_kernel<<<256 + M_TOTAL / 8, 256>>>(x, A, B);

    {
        static bool attr_set = false;
        if (!attr_set) {
            cudaFuncSetAttribute(lora_embed_kernel,
                                 cudaFuncAttributeMaxDynamicSharedMemorySize, SMEM_BYTES);
            attr_set = true;
        }
        lora_embed_kernel<<<CTAS, 256, SMEM_BYTES>>>(x, weight, out);
    }
}

// round 9
// speedup vs baseline: 1.0122x; 1.0122x over previous
#include <cuda_runtime.h>
#include <cuda_fp16.h>
#include <cstdint>

// ============================================================================
// y[t, :] = weight[x[t], :] + A[x[t], :] @ B
//   tokens M = 16384, DIM N = 1024, RANK K = 256
// mma.sync.m16n8k16.f32.f16.f16.f32, 2 CTAs/SM, ldmatrix both operands,
// 3-stage cp.async pipeline; epilogue weight rows cp.async-staged into dead
// pipeline buffers. PDL overlaps prep tail with main prologue.
// ============================================================================
static constexpr int M_TOTAL = 16384;
static constexpr int DIM     = 1024;
static constexpr int RANK    = 256;

static constexpr int TILE_M  = 128;
static constexpr int TILE_N  = 128;
static constexpr int KC      = 64;              // K chunk (halves)
static constexpr int STAGES  = 3;

// Smem: pitch 72 halves (144 B) -> conflict-free ldmatrix (banks 4i mod 32)
static constexpr int PITCH        = 72;
static constexpr int TILE_HALVES  = 128 * PITCH;            // 9216 halves
static constexpr int TILE_BYTES_S = TILE_HALVES * 2;        // 18432 B
static constexpr int STAGE_BYTES  = 2 * TILE_BYTES_S;       // A + B per stage
static constexpr int SMEM_BYTES   = STAGES * STAGE_BYTES + 512;  // 111104 B

// Weight staging: 64 rows x 528 B (132 floats) = 33792 B, fits one stage buf
static constexpr int W_PITCH_F = 132;
static constexpr int W_PITCH_B = 528;

// Scratch: half B^T [DIM][RANK] (0.5 MB), gathered half A [M][RANK] (8 MB)
__device__ __half g_Bt[DIM * RANK];
__device__ __half g_Ah[M_TOTAL * RANK];

// ---------------------------------------------------------------------------
__device__ __forceinline__ uint32_t smem_to_u32(const void* p) {
    uint32_t a;
    asm("{ .reg .u64 t; cvta.to.shared.u64 t, %1; cvt.u32.u64 %0, t; }" : "=r"(a) : "l"(p));
    return a;
}
__device__ __forceinline__ void cp_async16(uint32_t dst, const void* src) {
    asm volatile("cp.async.cg.shared.global [%0], [%1], 16;" :: "r"(dst), "l"(src));
}
__device__ __forceinline__ void cp_commit() {
    asm volatile("cp.async.commit_group;" ::: "memory");
}
template <int N>
__device__ __forceinline__ void cp_wait() {
    asm volatile("cp.async.wait_group %0;" :: "n"(N) : "memory");
}
__device__ __forceinline__ void ldmatrix_x4(uint32_t& r0, uint32_t& r1,
                                            uint32_t& r2, uint32_t& r3, uint32_t addr) {
    asm volatile("ldmatrix.sync.aligned.m8n8.x4.shared.b16 {%0,%1,%2,%3}, [%4];"
                 : "=r"(r0), "=r"(r1), "=r"(r2), "=r"(r3) : "r"(addr));
}
__device__ __forceinline__ void mma_f16(float* c, const uint32_t* a, const uint32_t* b) {
    asm volatile(
        "mma.sync.aligned.m16n8k16.row.col.f32.f16.f16.f32 "
        "{%0,%1,%2,%3}, {%4,%5,%6,%7}, {%8,%9}, {%0,%1,%2,%3};\n"
        : "+f"(c[0]), "+f"(c[1]), "+f"(c[2]), "+f"(c[3])
        : "r"(a[0]), "r"(a[1]), "r"(a[2]), "r"(a[3]), "r"(b[0]), "r"(b[1]));
}
__device__ __forceinline__ void stg_cs_v2(float* p, float x, float y) {
    asm volatile("st.global.cs.v2.f32 [%0], {%1,%2};" :: "l"(p), "f"(x), "f"(y) : "memory");
}

// ============================================================================
// Kernel 1 (fused prep):
//   blocks [0,256):     transpose+convert B -> g_Bt [DIM][RANK] half
//   blocks [256,2304):  gather+convert A rows: g_Ah[t] = half(A[x[t]]), 8 rows/blk
// Triggers programmatic launch completion after its stores.
// ============================================================================
__global__ __launch_bounds__(256)
void prep_kernel(const int* __restrict__ x, const float* __restrict__ A,
                 const float* __restrict__ B) {
    if (blockIdx.x < 256) {
        __shared__ float t[32][33];
        const int n0 = (blockIdx.x & 31) * 32;
        const int k0 = (blockIdx.x >> 5) * 32;
        const int tx = threadIdx.x & 31;
        const int ty = threadIdx.x >> 5;
        #pragma unroll
        for (int j = 0; j < 32; j += 8)
            t[ty + j][tx] = B[(size_t)(k0 + ty + j) * DIM + n0 + tx];
        __syncthreads();
        #pragma unroll
        for (int j = 0; j < 32; j += 8)
            g_Bt[(size_t)(n0 + ty + j) * RANK + k0 + tx] = __float2half_rn(t[tx][ty + j]);
    } else {
        const int row  = (blockIdx.x - 256) * 8 + (threadIdx.x >> 5);
        const int lane = threadIdx.x & 31;
        const int tok  = x[row];
        const float4* src = (const float4*)(A + (size_t)tok * RANK) + lane * 2;
        float4 v0 = src[0], v1 = src[1];
        __half2 h[4];
        h[0] = __floats2half2_rn(v0.x, v0.y);
        h[1] = __floats2half2_rn(v0.z, v0.w);
        h[2] = __floats2half2_rn(v1.x, v1.y);
        h[3] = __floats2half2_rn(v1.z, v1.w);
        *(uint4*)(g_Ah + (size_t)row * RANK + lane * 8) = *(const uint4*)h;
    }
#if __CUDA_ARCH__ >= 900
    cudaTriggerProgrammaticLaunchCompletion();
#endif
}

// ============================================================================
// Kernel 2: fused GEMM + weight-gather epilogue
//   grid: (8, 128) N fastest; block 256 = 8 warps; warp tile 64x32; 2 CTAs/SM
// ============================================================================
__global__ __launch_bounds__(256, 2)
void lora_embed_kernel(const int* __restrict__ x,
                       const float* __restrict__ weight,
                       float* __restrict__ out) {
    extern __shared__ __align__(16) char smem[];
    int* s_tok = (int*)(smem + STAGES * STAGE_BYTES);

    const int tid    = threadIdx.x;
    const int wid    = tid >> 5;
    const int lane   = tid & 31;
    const int group  = lane >> 2;   // 0..7
    const int tig    = lane & 3;    // 0..3
    const int warp_m = wid >> 2;    // 0..1
    const int warp_n = wid & 3;     // 0..3

    const int n0 = blockIdx.x * TILE_N;
    const int m0 = blockIdx.y * TILE_M;

    if (tid < 128) s_tok[tid] = x[m0 + tid];

    const uint32_t sb = smem_to_u32(smem);

    // Loader mapping: 2 threads per row, each covers 32 halves (4x16B) / chunk
    const int lrow  = tid >> 1;
    const int lhalf = tid & 1;
    const __half* a_src = g_Ah + (size_t)(m0 + lrow) * RANK + lhalf * 32;
    const __half* b_src = g_Bt + (size_t)(n0 + lrow) * RANK + lhalf * 32;
    const uint32_t a_dst = sb + (lrow * PITCH + lhalf * 32) * 2;
    const uint32_t b_dst = a_dst + TILE_BYTES_S;

    auto prefetch = [&](int c) {
        const uint32_t soff = (uint32_t)(c % STAGES) * STAGE_BYTES;
        #pragma unroll
        for (int i = 0; i < 4; i++) {
            cp_async16(a_dst + soff + i * 16, a_src + c * KC + i * 8);
            cp_async16(b_dst + soff + i * 16, b_src + c * KC + i * 8);
        }
        cp_commit();
    };

    // Stage 64 weight rows (half h) into dead stage buffer (1 + h).
    auto stage_weight = [&](int h) {
        const uint32_t dsm = sb + (uint32_t)(1 + h) * STAGE_BYTES;
        #pragma unroll
        for (int i = 0; i < 8; i++) {
            const int idx = tid + 256 * i;        // 0..2047
            const int row = idx >> 5;             // 0..63
            const int c16 = idx & 31;             // 16B chunk within 512B row
            const int tok = s_tok[h * 64 + row];
            cp_async16(dsm + (uint32_t)(row * W_PITCH_B + c16 * 16),
                       weight + (size_t)tok * DIM + n0 + c16 * 4);
        }
        cp_commit();
    };

    float acc[4][4][4];
    #pragma unroll
    for (int mt = 0; mt < 4; mt++)
        #pragma unroll
        for (int nt = 0; nt < 4; nt++)
            #pragma unroll
            for (int r = 0; r < 4; r++) acc[mt][nt][r] = 0.f;

    // A ldmatrix lane offset: row = warp_m*64 + (lane&15), koff = (lane>>4)*8
    const uint32_t a_lane_off =
        (uint32_t)(((warp_m * 64 + (lane & 15)) * PITCH + (lane >> 4) * 8) * 2);
    // B ldmatrix lane offset (x4 = mats [nlo klo, nlo khi, nhi klo, nhi khi])
    const uint32_t b_lane_off =
        (uint32_t)(((warp_n * 32 + ((lane >> 4) << 3) + (lane & 7)) * PITCH
                    + ((lane >> 3) & 1) * 8) * 2);

    auto compute = [&](int c) {
        const uint32_t abuf = sb + (uint32_t)(c % STAGES) * STAGE_BYTES;
        const uint32_t bbuf = abuf + (uint32_t)TILE_BYTES_S;
        #pragma unroll
        for (int ks = 0; ks < 4; ks++) {
            const uint32_t k0b = (uint32_t)(ks * 16 * 2);
            uint32_t af[4][4];
            #pragma unroll
            for (int mt = 0; mt < 4; mt++)
                ldmatrix_x4(af[mt][0], af[mt][1], af[mt][2], af[mt][3],
                            abuf + a_lane_off + (uint32_t)(mt * 16 * PITCH * 2) + k0b);
            uint32_t bf[4][2];
            #pragma unroll
            for (int q = 0; q < 2; q++)
                ldmatrix_x4(bf[2 * q][0], bf[2 * q][1], bf[2 * q + 1][0], bf[2 * q + 1][1],
                            bbuf + b_lane_off + (uint32_t)(q * 16 * PITCH * 2) + k0b);
            #pragma unroll
            for (int mt = 0; mt < 4; mt++)
                #pragma unroll
                for (int nt = 0; nt < 4; nt++)
                    mma_f16(acc[mt][nt], af[mt], bf[nt]);
        }
    };

    // PDL: block here (not earlier) so token/address setup overlaps prep tail.
#if __CUDA_ARCH__ >= 900
    cudaGridDependencySynchronize();
#endif

    // Pipeline (4 chunks, 3 stages). Groups: G0..G3 = pf0..pf3, G4=W0, G5=W1.
    // Each wait<1> forces exactly the needed group; final wait<0> drains W0/W1.
    prefetch(0);
    prefetch(1);

    cp_wait<1>(); __syncthreads(); prefetch(2);        compute(0);
    cp_wait<1>(); __syncthreads(); prefetch(3);        compute(1);
    cp_wait<1>(); __syncthreads(); stage_weight(0);    compute(2);
    cp_wait<1>(); __syncthreads(); stage_weight(1);    compute(3);
    cp_wait<0>(); __syncthreads();   // weight halves resident in smem

    // Epilogue: out = weight_smem + acc. warp_m selects the staged half.
    // Streaming stores (.cs): out is write-once; keep L2 for A/Bt/weight.
    const float* wsm = (const float*)(smem + (size_t)(1 + warp_m) * STAGE_BYTES);
    #pragma unroll
    for (int mt = 0; mt < 4; mt++) {
        #pragma unroll
        for (int mo = 0; mo < 2; mo++) {
            const int r = mt * 16 + mo * 8 + group;           // 0..63 in half
            const float* wrow = wsm + r * W_PITCH_F;
            float* orow = out + (size_t)(m0 + warp_m * 64 + r) * DIM + n0;
            #pragma unroll
            for (int nt = 0; nt < 4; nt++) {
                const int col = warp_n * 32 + nt * 8 + tig * 2;
                float2 w = *(const float2*)(wrow + col);
                stg_cs_v2(orow + col,
                          w.x + acc[mt][nt][mo * 2 + 0],
                          w.y + acc[mt][nt][mo * 2 + 1]);
            }
        }
    }
}

// ============================================================================
// Launch
// ============================================================================
extern "C" void kernel_launch(void* const* d_in, const int* in_sizes, int n_in,
                              void* d_out, int out_size) {
    const int*   x      = (const int*)d_in[0];       // [16384] int32
    const float* weight = (const float*)d_in[1];     // [128000, 1024]
    const float* A      = (const float*)d_in[2];     // [128000, 256]
    const float* B      = (const float*)d_in[3];     // [256, 1024]
    float* out          = (float*)d_out;             // [16384, 1024]

    (void)in_sizes; (void)n_in; (void)out_size;

    // Fused prep: 256 transpose blocks + 2048 gather blocks
    prep_kernel<<<256 + M_TOTAL / 8, 256>>>(x, A, B);

    {
        static bool attr_set = false;
        if (!attr_set) {
            cudaFuncSetAttribute(lora_embed_kernel,
                                 cudaFuncAttributeMaxDynamicSharedMemorySize, SMEM_BYTES);
            attr_set = true;
        }
        // PDL launch: main may start while prep drains; it blocks in
        // cudaGridDependencySynchronize() until all prep CTAs triggered.
        cudaLaunchConfig_t cfg = {};
        cfg.gridDim  = dim3(DIM / TILE_N, M_TOTAL / TILE_M);   // (8, 128)
        cfg.blockDim = dim3(256, 1, 1);
        cfg.dynamicSmemBytes = SMEM_BYTES;
        cfg.stream = 0;
        cudaLaunchAttribute attrs[1];
        attrs[0].id = cudaLaunchAttributeProgrammaticStreamSerialization;
        attrs[0].val.programmaticStreamSerializationAllowed = 1;
        cfg.attrs = attrs;
        cfg.numAttrs = 1;
        cudaError_t err = cudaLaunchKernelEx(&cfg, lora_embed_kernel, x, weight, out);
        if (err != cudaSuccess) {
            // Fallback: plain launch (PDL attribute unsupported in this context)
            cudaGetLastError();
            dim3 grid(DIM / TILE_N, M_TOTAL / TILE_M);
            lora_embed_kernel<<<grid, 256, SMEM_BYTES>>>(x, weight, out);
        }
    }
}